// round 1
// baseline (speedup 1.0000x reference)
#include <cuda_runtime.h>
#include <math.h>

#define N_NODES 10000
#define N_EDGES 320000
#define IN_DIM  512
#define CH      128

// ---------------- scratch (device globals; no allocation allowed) ----------------
__device__ float g_h  [N_NODES * CH];   // normalized hidden
__device__ float g_xw [N_NODES * CH];   // (h @ Wg^T) * dinv[row]
__device__ float g_z1 [N_NODES * CH];   // GCN output
__device__ float g_dinv[N_NODES];
__device__ int   g_cnt [N_NODES];
__device__ int   g_pos [N_NODES];
__device__ int   g_off [N_NODES + 1];
__device__ int   g_src [N_EDGES];
__device__ int   g_tgt [N_EDGES];
__device__ int   g_adj [N_EDGES];       // sources sorted by target (CSR payload)
__device__ float g_z2c0[N_NODES];

// ---------------- small utility kernels ----------------
__global__ void zero_kernel() {
    int i = blockIdx.x * blockDim.x + threadIdx.x;
    if (i < N_NODES) { g_cnt[i] = 0; g_pos[i] = 0; }
}

// Detect int64 vs int32 edge buffer: node ids < 10000, so an int64 buffer viewed
// as int32 has zeros at every odd index. Probability of false positive with
// genuine int32 random ids in [0,10000): (1e-4)^8 ~ 0. Deterministic per input.
__device__ __forceinline__ bool edges_are_i64(const int* p) {
    bool b = true;
#pragma unroll
    for (int i = 0; i < 8; i++) b = b && (p[2 * i + 1] == 0);
    return b;
}

__global__ void cvt_count_kernel(const int* __restrict__ ep) {
    int e = blockIdx.x * blockDim.x + threadIdx.x;
    if (e >= N_EDGES) return;
    int s, t;
    if (edges_are_i64(ep)) {
        const long long* p = (const long long*)ep;
        s = (int)p[e]; t = (int)p[N_EDGES + e];
    } else {
        s = ep[e]; t = ep[N_EDGES + e];
    }
    g_src[e] = s; g_tgt[e] = t;
    atomicAdd(&g_cnt[t], 1);
}

// single-block exclusive scan of g_cnt -> g_off, plus dinv = rsqrt(cnt+1)
__global__ void scan_kernel() {
    __shared__ int wsum[32];
    int tid = threadIdx.x, lane = tid & 31, wid = tid >> 5;
    int carry = 0;
    for (int base = 0; base < N_NODES; base += 1024) {
        int idx = base + tid;
        int v = (idx < N_NODES) ? g_cnt[idx] : 0;
        int x = v;
#pragma unroll
        for (int d = 1; d < 32; d <<= 1) {
            int y = __shfl_up_sync(0xffffffffu, x, d);
            if (lane >= d) x += y;
        }
        if (lane == 31) wsum[wid] = x;
        __syncthreads();
        if (wid == 0) {
            int s = wsum[lane];
#pragma unroll
            for (int d = 1; d < 32; d <<= 1) {
                int y = __shfl_up_sync(0xffffffffu, s, d);
                if (lane >= d) s += y;
            }
            wsum[lane] = s;
        }
        __syncthreads();
        int offset = wid ? wsum[wid - 1] : 0;
        if (idx < N_NODES) {
            g_off[idx] = carry + offset + x - v;               // exclusive
            g_dinv[idx] = rsqrtf((float)(v + 1));              // deg incl self-loop, >0
        }
        carry += wsum[31];
        __syncthreads();
    }
    if (tid == 0) g_off[N_NODES] = carry;
}

__global__ void fill_kernel() {
    int e = blockIdx.x * blockDim.x + threadIdx.x;
    if (e >= N_EDGES) return;
    int t = g_tgt[e];
    int p = atomicAdd(&g_pos[t], 1);
    g_adj[g_off[t] + p] = g_src[e];
}

// ---------------- tiled fp32 GEMM: out[M,128] = A[M,K] @ W[128,K]^T ----------------
// NORM: add bias, L2-normalize rows, multiply by `scale`.
// ROWSCALE: multiply output row m by rs[m] (used to fold dinv into xw).
template <int KDIM, bool NORM, bool ROWSCALE>
__global__ void gemm_kernel(const float* __restrict__ A, const float* __restrict__ W,
                            const float* __restrict__ bias, const float* __restrict__ rs,
                            float* __restrict__ out, int M, float scale) {
    constexpr int BM = 64, BN = 128, BK = 32;
    __shared__ float As[BM][BK + 4];    // [m][k], stride 36 (16B-aligned rows)
    __shared__ float Bs[BK][BN + 4];    // [k][n], stride 132
    __shared__ float ssq[BM];

    int tid = threadIdx.x;
    int m0 = blockIdx.x * BM;
    int tr = tid >> 4, tc = tid & 15;   // 16 x 16 thread grid -> 4 x 8 micro-tile

    float acc[4][8];
#pragma unroll
    for (int i = 0; i < 4; i++)
#pragma unroll
        for (int j = 0; j < 8; j++) acc[i][j] = 0.f;

    for (int kt = 0; kt < KDIM; kt += BK) {
        // A tile: 64 rows x 8 float4, 2 per thread
#pragma unroll
        for (int h = 0; h < 2; h++) {
            int m = (tid >> 3) + h * 32;
            int q = tid & 7;
            float4 v = make_float4(0.f, 0.f, 0.f, 0.f);
            int gm = m0 + m;
            if (gm < M) v = *(const float4*)(A + (size_t)gm * KDIM + kt + q * 4);
            *(float4*)&As[m][q * 4] = v;
        }
        // W tile: 128 rows x 8 float4, 4 per thread, transposed into Bs[k][n]
#pragma unroll
        for (int h = 0; h < 4; h++) {
            int idx = tid + h * 256;
            int n = idx >> 3, q = idx & 7;
            float4 v = *(const float4*)(W + (size_t)n * KDIM + kt + q * 4);
            Bs[q * 4 + 0][n] = v.x; Bs[q * 4 + 1][n] = v.y;
            Bs[q * 4 + 2][n] = v.z; Bs[q * 4 + 3][n] = v.w;
        }
        __syncthreads();
#pragma unroll
        for (int k = 0; k < BK; k++) {
            float a[4], b[8];
#pragma unroll
            for (int i = 0; i < 4; i++) a[i] = As[tr * 4 + i][k];
            *(float4*)&b[0] = *(const float4*)&Bs[k][tc * 8];
            *(float4*)&b[4] = *(const float4*)&Bs[k][tc * 8 + 4];
#pragma unroll
            for (int i = 0; i < 4; i++)
#pragma unroll
                for (int j = 0; j < 8; j++) acc[i][j] = fmaf(a[i], b[j], acc[i][j]);
        }
        __syncthreads();
    }

    if (bias) {
        float bj[8];
#pragma unroll
        for (int j = 0; j < 8; j++) bj[j] = bias[tc * 8 + j];
#pragma unroll
        for (int i = 0; i < 4; i++)
#pragma unroll
            for (int j = 0; j < 8; j++) acc[i][j] += bj[j];
    }

    float rowmul[4];
#pragma unroll
    for (int i = 0; i < 4; i++) rowmul[i] = 1.f;

    if (NORM) {
        if (tid < BM) ssq[tid] = 0.f;
        __syncthreads();
#pragma unroll
        for (int i = 0; i < 4; i++) {
            float p = 0.f;
#pragma unroll
            for (int j = 0; j < 8; j++) p += acc[i][j] * acc[i][j];
            atomicAdd(&ssq[tr * 4 + i], p);
        }
        __syncthreads();
#pragma unroll
        for (int i = 0; i < 4; i++)
            rowmul[i] = scale / fmaxf(sqrtf(ssq[tr * 4 + i]), 1e-12f);
    }
    if (ROWSCALE) {
#pragma unroll
        for (int i = 0; i < 4; i++) {
            int gm = m0 + tr * 4 + i;
            if (gm < M) rowmul[i] *= rs[gm];
        }
    }

#pragma unroll
    for (int i = 0; i < 4; i++) {
        int gm = m0 + tr * 4 + i;
        if (gm >= M) continue;
        float4 o0, o1;
        o0.x = acc[i][0] * rowmul[i]; o0.y = acc[i][1] * rowmul[i];
        o0.z = acc[i][2] * rowmul[i]; o0.w = acc[i][3] * rowmul[i];
        o1.x = acc[i][4] * rowmul[i]; o1.y = acc[i][5] * rowmul[i];
        o1.z = acc[i][6] * rowmul[i]; o1.w = acc[i][7] * rowmul[i];
        *(float4*)(out + (size_t)gm * CH + tc * 8)     = o0;
        *(float4*)(out + (size_t)gm * CH + tc * 8 + 4) = o1;
    }
}

// ---------------- GCN gather: z1[i] = dinv[i]*(xws[i] + sum_in xws[s]) + bg ----------------
// g_xw already contains (h@Wg^T)[s] * dinv[s]
__global__ void gather_kernel(const float* __restrict__ bg) {
    int i = blockIdx.x;
    int c = threadIdx.x;   // 128 threads, one channel each
    float di = g_dinv[i];
    float acc = g_xw[i * CH + c];             // self loop: xw[i]*dinv[i] (then *di below)
    int s0 = g_off[i], s1 = g_off[i + 1];
    for (int j = s0; j < s1; j++) {
        int s = g_adj[j];
        acc += g_xw[s * CH + c];
    }
    g_z1[i * CH + c] = acc * di + bg[c];
}

// ---------------- z2 column 0: per row of x2, dot with W22 rows, L2-normalize ----------------
__global__ void z2_kernel(const float* __restrict__ x2, const float* __restrict__ W22) {
    int i = blockIdx.x;
    int tid = threadIdx.x, lane = tid & 31, wid = tid >> 5;
    const float4* xr = (const float4*)(x2 + (size_t)i * N_NODES);
    const float4* w0 = (const float4*)W22;
    const float4* w1 = (const float4*)(W22 + N_NODES);
    float s0 = 0.f, s1 = 0.f;
    for (int j = tid; j < N_NODES / 4; j += 256) {
        float4 a = xr[j], b = w0[j], c = w1[j];
        s0 += a.x * b.x + a.y * b.y + a.z * b.z + a.w * b.w;
        s1 += a.x * c.x + a.y * c.y + a.z * c.z + a.w * c.w;
    }
#pragma unroll
    for (int d = 16; d; d >>= 1) {
        s0 += __shfl_xor_sync(0xffffffffu, s0, d);
        s1 += __shfl_xor_sync(0xffffffffu, s1, d);
    }
    __shared__ float r0[8], r1[8];
    if (lane == 0) { r0[wid] = s0; r1[wid] = s1; }
    __syncthreads();
    if (tid == 0) {
        float y0 = 0.f, y1 = 0.f;
#pragma unroll
        for (int k = 0; k < 8; k++) { y0 += r0[k]; y1 += r1[k]; }
        float n = fmaxf(sqrtf(y0 * y0 + y1 * y1), 1e-12f);
        g_z2c0[i] = 0.8f * y0 / n;
    }
}

// ---------------- decoder: warp per edge ----------------
__global__ void decoder_kernel(float* __restrict__ out) {
    int gw = (blockIdx.x * blockDim.x + threadIdx.x) >> 5;
    int lane = threadIdx.x & 31;
    if (gw >= N_EDGES) return;
    int r = g_src[gw], c = g_tgt[gw];
    const float4* zr = (const float4*)(g_z1 + (size_t)r * CH);
    const float4* zc = (const float4*)(g_z1 + (size_t)c * CH);
    float4 a = zr[lane], b = zc[lane];
    float d = a.x * b.x + a.y * b.y + a.z * b.z + a.w * b.w;
#pragma unroll
    for (int o = 16; o; o >>= 1) d += __shfl_xor_sync(0xffffffffu, d, o);
    if (lane == 0) {
        float vn = g_z2c0[r] + g_z2c0[c];
        float sf = 1.f / (1.f + __expf(-d));
        float sn = 1.f / (1.f + __expf(-vn));
        out[gw] = sf * sf + (1.f - sf) * sn;
    }
}

// ---------------- launch ----------------
extern "C" void kernel_launch(void* const* d_in, const int* in_sizes, int n_in,
                              void* d_out, int out_size) {
    const float* x    = (const float*)d_in[0];
    const float* x2   = (const float*)d_in[1];
    const float* W2   = (const float*)d_in[2];
    const float* b2   = (const float*)d_in[3];
    const float* Wg   = (const float*)d_in[4];
    const float* bg   = (const float*)d_in[5];
    const float* W22  = (const float*)d_in[6];
    const int*   edge = (const int*)d_in[7];
    float* out = (float*)d_out;

    float *p_h, *p_xw, *p_dinv;
    cudaGetSymbolAddress((void**)&p_h, g_h);
    cudaGetSymbolAddress((void**)&p_xw, g_xw);
    cudaGetSymbolAddress((void**)&p_dinv, g_dinv);

    zero_kernel<<<(N_NODES + 255) / 256, 256>>>();
    cvt_count_kernel<<<(N_EDGES + 255) / 256, 256>>>(edge);
    scan_kernel<<<1, 1024>>>();
    fill_kernel<<<(N_EDGES + 255) / 256, 256>>>();

    // h = normalize(x @ W2^T + b2) * 1.8
    gemm_kernel<IN_DIM, true, false><<<(N_NODES + 63) / 64, 256>>>(
        x, W2, b2, nullptr, p_h, N_NODES, 1.8f);
    // xw = (h @ Wg^T) * dinv[row]
    gemm_kernel<CH, false, true><<<(N_NODES + 63) / 64, 256>>>(
        p_h, Wg, nullptr, p_dinv, p_xw, N_NODES, 1.0f);

    gather_kernel<<<N_NODES, CH>>>(bg);
    z2_kernel<<<N_NODES, 256>>>(x2, W22);
    decoder_kernel<<<(N_EDGES * 32 + 255) / 256, 256>>>(out);
}